// round 3
// baseline (speedup 1.0000x reference)
#include <cuda_runtime.h>
#include <math.h>
#include <stdint.h>

// RVQE: 12-qubit real statevector recurrent cell, B=64, T=9 (8 scan steps).
// One CTA per batch element; state = 4096 floats = 128 threads x 32 registers.
// Global amplitude index g (12 bits): bit (11-l) <-> lane l.
//   local bits 0..4 (within thread): lanes 11(anc1)=bit0, 10(anc0)=bit1, 9=bit2, 8=bit3, 7=bit4
//   thread bits 0..4 (warp lane):    lanes 6,5,4,3,2   -> __shfl_xor
//   thread bits 5,6  (warp id):      lanes 1,0         -> smem exchange
//
// Neuron algebra (verified identity): R(a) C R(-a) = G C, where G rotates anc0 by
// (2 x_out - 1)*theta_out on anc1=1 sectors. Hence
//   neuron_n = F-part ... : temporal sequence  R(a_n), K+, C_n, G_n, K-, R(-a_n)
// Chained over n with R(-a_n)R(a_{n+1}) = R(Delta):
//   stage chain = E(a_0) C_0 G_0 T'(D1) C_1 G_1 ... T'(D9) C_9 G_9 F(a_9)
//   E(a)  = temporal [R(a), K+]
//   T'(D) = temporal [K-, R(D), K+]
//   F(a)  = temporal [K-, R(-a)]
// F is applied explicitly at end of every stage (it does NOT commute with the
// next stage's RYs — round-2 bug).

namespace {

constexpr int NTH   = 128;
constexpr int TT    = 9;
constexpr int NSTEP = 8;
constexpr int NIDX  = 22;   // 18 deltas + 2 entries + 2 trailings

__device__ __forceinline__ void ry_pair(float& a, float& b, float c, float s) {
    float a0 = a, b0 = b;
    a = fmaf(-s, b0, c * a0);
    b = fmaf( s, a0, c * b0);
}

template <int K>
__device__ __forceinline__ void ry_local(float* v, float c, float s) {
#pragma unroll
    for (int r = 0; r < 32; r++)
        if (!(r & (1 << K))) ry_pair(v[r], v[r | (1 << K)], c, s);
}

__device__ __forceinline__ void ry_shfl(float* v, int t, int m, float c, float s) {
    float se = (t & m) ? s : -s;
#pragma unroll
    for (int r = 0; r < 32; r++) {
        float w = __shfl_xor_sync(0xffffffffu, v[r], m);
        v[r] = fmaf(se, w, c * v[r]);
    }
}

// Combined RY(lane0) * RY(lane1): one smem round-trip, 4-way gather.
__device__ __forceinline__ void ry_smem2(float* v, int t,
                                         float c0, float s0, float c1, float s1,
                                         float* exch) {
#pragma unroll
    for (int r = 0; r < 32; r++) exch[t * 33 + r] = v[r];
    __syncthreads();
    int a  = (t >> 6) & 1;
    int bb = (t >> 5) & 1;
    float r0a0 = a  ? s0 : c0;
    float r0a1 = a  ? c0 : -s0;
    float r1b0 = bb ? s1 : c1;
    float r1b1 = bb ? c1 : -s1;
    float k00 = r0a0 * r1b0, k01 = r0a0 * r1b1;
    float k10 = r0a1 * r1b0, k11 = r0a1 * r1b1;
    int base = t & 31;
    const float* x00 = exch + base * 33;
    const float* x01 = exch + (base | 32) * 33;
    const float* x10 = exch + (base | 64) * 33;
    const float* x11 = exch + (base | 96) * 33;
#pragma unroll
    for (int r = 0; r < 32; r++) {
        v[r] = fmaf(k00, x00[r],
               fmaf(k01, x01[r],
               fmaf(k10, x10[r], k11 * x11[r])));
    }
    __syncthreads();
}

// C = CiY(target = local bit K, sign=+1, ctrl anc1 (local bit0 == 1))
template <int K>
__device__ __forceinline__ void ciy_local(float* v) {
#pragma unroll
    for (int r = 0; r < 32; r++)
        if ((r & 1) && !(r & (1 << K))) {
            float p0 = v[r];
            v[r] = v[r | (1 << K)];
            v[r | (1 << K)] = -p0;
        }
}

__device__ __forceinline__ void ciy_shfl(float* v, int t, int m) {
    float se = (t & m) ? -1.f : 1.f;
#pragma unroll
    for (int i = 0; i < 16; i++) {
        int r = 2 * i + 1;
        float w = __shfl_xor_sync(0xffffffffu, v[r], m);
        v[r] = se * w;
    }
}

__device__ __forceinline__ void ciy_smem(float* v, int t, int m, float* exch) {
#pragma unroll
    for (int i = 0; i < 16; i++) exch[t * 33 + i] = v[2 * i + 1];
    __syncthreads();
    int p = t ^ m;
    float se = (t & m) ? -1.f : 1.f;
#pragma unroll
    for (int i = 0; i < 16; i++) v[2 * i + 1] = se * exch[p * 33 + i];
    __syncthreads();
}

// v index r = (g<<2) | (anc0<<1) | anc1: x0=(0,0) x1=(0,1) x2=(1,0) x3=(1,1)

// T'(D) = temporal [K-, R(D), K+]:
//   x0' =  c x0 + s x3 ;  x1' = c x1 - s x2 ;  x2' = s x1 + c x2 ;  x3' = -s x0 + c x3
__device__ __forceinline__ void applyT(float* v, float cb, float sb,
                                       const float* dc, const float* ds) {
#pragma unroll
    for (int g = 0; g < 8; g++) {
        float dcv = dc[g], dsv = ds[g];
        float c = fmaf(cb, dcv, -sb * dsv);
        float s = fmaf(sb, dcv,  cb * dsv);
        float x0 = v[4*g+0], x1 = v[4*g+1], x2 = v[4*g+2], x3 = v[4*g+3];
        v[4*g+0] = fmaf( s, x3, c * x0);
        v[4*g+1] = fmaf(-s, x2, c * x1);
        v[4*g+2] = fmaf( s, x1, c * x2);
        v[4*g+3] = fmaf(-s, x0, c * x3);
    }
}

// E(a) = temporal [R(a), K+]:
//   x0' = c x0 - s x2 ; x1' = c x1 - s x3 ; x2' = s x1 + c x3 ; x3' = -(s x0 + c x2)
__device__ __forceinline__ void applyE(float* v, float cb, float sb,
                                       const float* dc, const float* ds) {
#pragma unroll
    for (int g = 0; g < 8; g++) {
        float dcv = dc[g], dsv = ds[g];
        float c = fmaf(cb, dcv, -sb * dsv);
        float s = fmaf(sb, dcv,  cb * dsv);
        float x0 = v[4*g+0], x1 = v[4*g+1], x2 = v[4*g+2], x3 = v[4*g+3];
        v[4*g+0] = fmaf(-s, x2, c * x0);
        v[4*g+1] = fmaf(-s, x3, c * x1);
        v[4*g+2] = fmaf( s, x1, c * x3);
        v[4*g+3] = -fmaf( s, x0, c * x2);
    }
}

// F(a) = temporal [K-, R(-a)]:
//   x0' = c x0 - s x3 ; x1' = c x1 + s x2 ; x2' = -(s x0 + c x3) ; x3' = -s x1 + c x2
__device__ __forceinline__ void applyF(float* v, float cb, float sb,
                                       const float* dc, const float* ds) {
#pragma unroll
    for (int g = 0; g < 8; g++) {
        float dcv = dc[g], dsv = ds[g];
        float c = fmaf(cb, dcv, -sb * dsv);
        float s = fmaf(sb, dcv,  cb * dsv);
        float x0 = v[4*g+0], x1 = v[4*g+1], x2 = v[4*g+2], x3 = v[4*g+3];
        v[4*g+0] = fmaf(-s, x3, c * x0);
        v[4*g+1] = fmaf( s, x2, c * x1);
        v[4*g+2] = -fmaf( s, x0, c * x3);
        v[4*g+3] = fmaf(-s, x1, c * x2);
    }
}

// G: rotate (x1,x3) (anc0 pair on anc1=1) by signed angle; se carries the sign.
__device__ __forceinline__ void applyG(float* v, float c, float se) {
#pragma unroll
    for (int g = 0; g < 8; g++) {
        float x1 = v[4*g+1], x3 = v[4*g+3];
        v[4*g+1] = fmaf(-se, x3, c * x1);
        v[4*g+3] = fmaf( se, x1, c * x3);
    }
}
template <int GB>  // sign from g bit GB (lanes 7..9)
__device__ __forceinline__ void applyGg(float* v, float c, float s) {
#pragma unroll
    for (int g = 0; g < 8; g++) {
        float se = (g & (1 << GB)) ? s : -s;
        float x1 = v[4*g+1], x3 = v[4*g+3];
        v[4*g+1] = fmaf(-se, x3, c * x1);
        v[4*g+3] = fmaf( se, x1, c * x3);
    }
}

__global__ void __launch_bounds__(NTH, 1) rvqe_kernel(
    const int*   __restrict__ inputs,   // (64, 9, 6) int32
    const float* __restrict__ ua,       // (2, 10)
    const float* __restrict__ nth,      // (2, 10, 11)
    float*       __restrict__ out,
    int out_size)
{
    __shared__ float exch[NTH * 33];
    __shared__ float uc[20], us[20];
    __shared__ float dcs[NIDX][8], dss[NIDX][8];
    __shared__ float cbs[NIDX][NTH], sbs[NIDX][NTH];
    __shared__ float gc_sm[20], gs_sm[20];     // G angles: cos/sin(theta_row[n]/2)
    __shared__ float probs_sm[64];
    __shared__ int   tIdx[TT];

    const int t = threadIdx.x;
    const int b = blockIdx.x;
    const int* inb = inputs + b * TT * 6;

    //  0.. 8 : stage0 deltas  row(0,n) - row(0,n-1), n=1..9
    //  9..17 : stage1 deltas  row(1,n) - row(1,n-1), n=1..9
    //  18,19 : entries  row(0,0), row(1,0)
    //  20,21 : trailing row(0,9), row(1,9)
    const int aIdx[NIDX] = {1,2,3,4,5,6,7,8,9, 11,12,13,14,15,16,17,18,19, 0, 10, 9, 19};
    const int bIdx[NIDX] = {0,1,2,3,4,5,6,7,8, 10,11,12,13,14,15,16,17,18, -1,-1,-1,-1};

    // ---- precompute ----
    if (t < 20) {
        float c, s; sincosf(0.5f * ua[t], &s, &c);
        uc[t] = c; us[t] = s;
        float cg, sg; sincosf(0.5f * nth[t * 11 + (t % 10)], &sg, &cg);
        gc_sm[t] = cg; gs_sm[t] = sg;
    }
    for (int idx = 0; idx < NIDX; idx++) {
        const float* A = nth + aIdx[idx] * 11;
        const float* Bp = (bIdx[idx] >= 0) ? (nth + bIdx[idx] * 11) : nullptr;
        float base = A[10] - (Bp ? Bp[10] : 0.f);
#pragma unroll
        for (int i = 0; i < 7; i++)            // lane i -> thread bit (6-i)
            if ((t >> (6 - i)) & 1) base += A[i] - (Bp ? Bp[i] : 0.f);
        float c, s; sincosf(0.5f * base, &s, &c);
        cbs[idx][t] = c; sbs[idx][t] = s;
    }
    for (int j = t; j < NIDX * 8; j += NTH) {
        int idx = j >> 3, g = j & 7;
        const float* A = nth + aIdx[idx] * 11;
        const float* Bp = (bIdx[idx] >= 0) ? (nth + bIdx[idx] * 11) : nullptr;
        float d = 0.f;
        if (g & 1) d += A[9] - (Bp ? Bp[9] : 0.f);   // g bit0 = lane9
        if (g & 2) d += A[8] - (Bp ? Bp[8] : 0.f);   // g bit1 = lane8
        if (g & 4) d += A[7] - (Bp ? Bp[7] : 0.f);   // g bit2 = lane7
        float c, s; sincosf(0.5f * d, &s, &c);
        dcs[idx][g] = c; dss[idx][g] = s;
    }
    if (t < TT) {
        int idx = 0;
#pragma unroll
        for (int i = 0; i < 6; i++) idx |= (inb[t * 6 + i] & 1) << (5 - i);
        tIdx[t] = idx;
    }
    __syncthreads();

    // ---- init state ----
    float v[32];
#pragma unroll
    for (int r = 0; r < 32; r++) v[r] = 0.f;
    if (t == (tIdx[0] << 1)) v[0] = 1.f;

    for (int step = 0; step < NSTEP; step++) {
        for (int s = 0; s < 2; s++) {
            const float* ucc = uc + s * 10;
            const float* uss = us + s * 10;
            // stage RYs
            ry_local<2>(v, ucc[9], uss[9]);
            ry_local<3>(v, ucc[8], uss[8]);
            ry_local<4>(v, ucc[7], uss[7]);
            for (int l = 2; l <= 6; l++)
                ry_shfl(v, t, 1 << (6 - l), ucc[l], uss[l]);
            ry_smem2(v, t, ucc[0], uss[0], ucc[1], uss[1], exch);

            // neuron chain: E C0 G0 T' C1 G1 ... T' C9 G9 F
            const int dbase = s * 9;
            applyE(v, cbs[18 + s][t], sbs[18 + s][t], dcs[18 + s], dss[18 + s]);
            // n = 0: C on lane0 (thread bit6, m=64), G sign from bit6
            ciy_smem(v, t, 64, exch);
            {
                float cg = gc_sm[s * 10 + 0], sg = gs_sm[s * 10 + 0];
                applyG(v, cg, ((t >> 6) & 1) ? sg : -sg);
            }
#pragma unroll
            for (int n = 1; n < 10; n++) {
                int di = dbase + n - 1;
                applyT(v, cbs[di][t], sbs[di][t], dcs[di], dss[di]);
                if (n >= 7) {
                    if (n == 7)      ciy_local<4>(v);
                    else if (n == 8) ciy_local<3>(v);
                    else             ciy_local<2>(v);
                } else if (n >= 2) {
                    ciy_shfl(v, t, 1 << (6 - n));
                } else {
                    ciy_smem(v, t, 32, exch);
                }
                float cg = gc_sm[s * 10 + n], sg = gs_sm[s * 10 + n];
                if (n <= 6)      applyG(v, cg, ((t >> (6 - n)) & 1) ? sg : -sg);
                else if (n == 7) applyGg<2>(v, cg, sg);
                else if (n == 8) applyGg<1>(v, cg, sg);
                else             applyGg<0>(v, cg, sg);
            }
            applyF(v, cbs[20 + s][t], sbs[20 + s][t], dcs[20 + s], dss[20 + s]);
        }

        // ---- probs over lanes 0..5 ----
        float ssq = 0.f;
#pragma unroll
        for (int r = 0; r < 32; r++) ssq = fmaf(v[r], v[r], ssq);
        float tot = ssq + __shfl_xor_sync(0xffffffffu, ssq, 1);
        if (!(t & 1)) {
            probs_sm[t >> 1] = tot;
            out[(b * NSTEP + step) * 64 + (t >> 1)] = tot;
        }
        __syncthreads();

        // ---- project + normalize; cond_flips cancel across steps ----
        int tj = tIdx[step + 1];
        float invn = 1.0f / sqrtf(probs_sm[tj]);
        if ((t >> 1) == tj) {
#pragma unroll
            for (int r = 0; r < 32; r++) v[r] *= invn;
        } else {
#pragma unroll
            for (int r = 0; r < 32; r++) v[r] = 0.f;
        }
    }

    // ---- second tuple output: measured = inputs[:,1:] as float ----
    if (out_size > 32768 && t < 48) {
        out[32768 + b * 48 + t] = (float)inb[6 + t];
    }
}

} // namespace

extern "C" void kernel_launch(void* const* d_in, const int* in_sizes, int n_in,
                              void* d_out, int out_size) {
    const int*   inputs = nullptr;
    const float* ua     = nullptr;
    const float* nth    = nullptr;
    for (int i = 0; i < n_in; i++) {
        if (in_sizes[i] == 3456)      inputs = (const int*)d_in[i];
        else if (in_sizes[i] == 20)   ua     = (const float*)d_in[i];
        else if (in_sizes[i] == 220)  nth    = (const float*)d_in[i];
    }
    rvqe_kernel<<<64, NTH>>>(inputs, ua, nth, (float*)d_out, out_size);
}

// round 5
// speedup vs baseline: 1.8669x; 1.8669x over previous
#include <cuda_runtime.h>
#include <math.h>
#include <stdint.h>

// RVQE: 12-qubit real statevector recurrent cell, B=64, T=9 (8 scan steps).
// One CTA per batch element; state = 4096 floats = 256 threads x 16 registers.
// Global amplitude index g (12 bits), g = (t << 4) | r:
//   r bits (local):  bit0=lane11(anc1), bit1=lane10(anc0), bit2=lane9, bit3=lane8
//   t bits 0..4 (warp lane): lanes 7,6,5,4,3  -> __shfl_xor (mask 1<<(7-lane))
//   t bits 5,6,7 (warp id):  lanes 2,1,0      -> smem exchange
//
// Fused neuron algebra (validated in round 3): per stage
//   chain = E(a_0) C_0 G_0 T'(D1) C_1 G_1 ... T'(D9) C_9 G_9 F(a_9)
//   E(a)  = temporal [R(a), K+] ;  T'(D) = [K-, R(D), K+] ;  F(a) = [K-, R(-a)]
//   G_n   = rotation of anc0 on anc1=1 sectors, angle sign from outlane-n bit.
// F applied explicitly at stage end (does not commute with next stage RYs).

namespace {

constexpr int NTH   = 256;
constexpr int TT    = 9;
constexpr int NSTEP = 8;
constexpr int NIDX  = 22;   // 18 deltas + 2 entries + 2 trailings
constexpr int EP    = 17;   // exch padding stride (odd -> conflict-free)

__device__ __forceinline__ void ry_pair(float& a, float& b, float c, float s) {
    float a0 = a, b0 = b;
    a = fmaf(-s, b0, c * a0);
    b = fmaf( s, a0, c * b0);
}

template <int K>
__device__ __forceinline__ void ry_local(float* v, float c, float s) {
#pragma unroll
    for (int r = 0; r < 16; r++)
        if (!(r & (1 << K))) ry_pair(v[r], v[r | (1 << K)], c, s);
}

__device__ __forceinline__ void ry_shfl(float* v, int t, int m, float c, float s) {
    float se = (t & m) ? s : -s;
#pragma unroll
    for (int r = 0; r < 16; r++) {
        float w = __shfl_xor_sync(0xffffffffu, v[r], m);
        v[r] = fmaf(se, w, c * v[r]);
    }
}

// Combined RY(lane0)*RY(lane1): t bits 7,6. One smem round-trip, 4-way gather.
__device__ __forceinline__ void ry_smem4(float* v, int t,
                                         float c0, float s0, float c1, float s1,
                                         float* exch) {
#pragma unroll
    for (int r = 0; r < 16; r++) exch[t * EP + r] = v[r];
    __syncthreads();
    int a  = (t >> 7) & 1;   // lane0 bit
    int bb = (t >> 6) & 1;   // lane1 bit
    float r0a0 = a  ? s0 : c0;
    float r0a1 = a  ? c0 : -s0;
    float r1b0 = bb ? s1 : c1;
    float r1b1 = bb ? c1 : -s1;
    float k00 = r0a0 * r1b0, k01 = r0a0 * r1b1;
    float k10 = r0a1 * r1b0, k11 = r0a1 * r1b1;
    int base = t & 63;
    const float* x00 = exch + base * EP;
    const float* x01 = exch + (base | 64)  * EP;   // lane1 flipped
    const float* x10 = exch + (base | 128) * EP;   // lane0 flipped
    const float* x11 = exch + (base | 192) * EP;
#pragma unroll
    for (int r = 0; r < 16; r++) {
        v[r] = fmaf(k00, x00[r],
               fmaf(k01, x01[r],
               fmaf(k10, x10[r], k11 * x11[r])));
    }
    __syncthreads();
}

// RY on lane2 (t bit5): 2-way smem exchange of all 16 elements.
__device__ __forceinline__ void ry_smem1(float* v, int t, float c, float s,
                                         float* exch) {
#pragma unroll
    for (int r = 0; r < 16; r++) exch[t * EP + r] = v[r];
    __syncthreads();
    const float* xp = exch + (t ^ 32) * EP;
    float se = (t & 32) ? s : -s;
#pragma unroll
    for (int r = 0; r < 16; r++) v[r] = fmaf(se, xp[r], c * v[r]);
    __syncthreads();
}

// C = CiY(target = local r bit K, ctrl anc1 (r bit0 == 1))
template <int K>
__device__ __forceinline__ void ciy_local(float* v) {
#pragma unroll
    for (int r = 0; r < 16; r++)
        if ((r & 1) && !(r & (1 << K))) {
            float p0 = v[r];
            v[r] = v[r | (1 << K)];
            v[r | (1 << K)] = -p0;
        }
}

__device__ __forceinline__ void ciy_shfl(float* v, int t, int m) {
    float se = (t & m) ? -1.f : 1.f;
#pragma unroll
    for (int i = 0; i < 8; i++) {
        int r = 2 * i + 1;
        float w = __shfl_xor_sync(0xffffffffu, v[r], m);
        v[r] = se * w;
    }
}

__device__ __forceinline__ void ciy_smem(float* v, int t, int m, float* exch) {
#pragma unroll
    for (int i = 0; i < 8; i++) exch[t * EP + i] = v[2 * i + 1];
    __syncthreads();
    int p = t ^ m;
    float se = (t & m) ? -1.f : 1.f;
#pragma unroll
    for (int i = 0; i < 8; i++) v[2 * i + 1] = se * exch[p * EP + i];
    __syncthreads();
}

// v index r = (g<<2)|(anc0<<1)|anc1, g in 0..3: x0=(0,0) x1=(0,1) x2=(1,0) x3=(1,1)

// T'(D) = temporal [K-, R(D), K+]
__device__ __forceinline__ void applyT(float* v, float cb, float sb,
                                       const float* dc, const float* ds) {
#pragma unroll
    for (int g = 0; g < 4; g++) {
        float dcv = dc[g], dsv = ds[g];
        float c = fmaf(cb, dcv, -sb * dsv);
        float s = fmaf(sb, dcv,  cb * dsv);
        float x0 = v[4*g+0], x1 = v[4*g+1], x2 = v[4*g+2], x3 = v[4*g+3];
        v[4*g+0] = fmaf( s, x3, c * x0);
        v[4*g+1] = fmaf(-s, x2, c * x1);
        v[4*g+2] = fmaf( s, x1, c * x2);
        v[4*g+3] = fmaf(-s, x0, c * x3);
    }
}

// E(a) = temporal [R(a), K+]
__device__ __forceinline__ void applyE(float* v, float cb, float sb,
                                       const float* dc, const float* ds) {
#pragma unroll
    for (int g = 0; g < 4; g++) {
        float dcv = dc[g], dsv = ds[g];
        float c = fmaf(cb, dcv, -sb * dsv);
        float s = fmaf(sb, dcv,  cb * dsv);
        float x0 = v[4*g+0], x1 = v[4*g+1], x2 = v[4*g+2], x3 = v[4*g+3];
        v[4*g+0] = fmaf(-s, x2, c * x0);
        v[4*g+1] = fmaf(-s, x3, c * x1);
        v[4*g+2] = fmaf( s, x1, c * x3);
        v[4*g+3] = -fmaf( s, x0, c * x2);
    }
}

// F(a) = temporal [K-, R(-a)]
__device__ __forceinline__ void applyF(float* v, float cb, float sb,
                                       const float* dc, const float* ds) {
#pragma unroll
    for (int g = 0; g < 4; g++) {
        float dcv = dc[g], dsv = ds[g];
        float c = fmaf(cb, dcv, -sb * dsv);
        float s = fmaf(sb, dcv,  cb * dsv);
        float x0 = v[4*g+0], x1 = v[4*g+1], x2 = v[4*g+2], x3 = v[4*g+3];
        v[4*g+0] = fmaf(-s, x3, c * x0);
        v[4*g+1] = fmaf( s, x2, c * x1);
        v[4*g+2] = -fmaf( s, x0, c * x3);
        v[4*g+3] = fmaf(-s, x1, c * x2);
    }
}

// G: rotate (x1,x3) by signed angle; se carries sign (thread-uniform).
__device__ __forceinline__ void applyG(float* v, float c, float se) {
#pragma unroll
    for (int g = 0; g < 4; g++) {
        float x1 = v[4*g+1], x3 = v[4*g+3];
        v[4*g+1] = fmaf(-se, x3, c * x1);
        v[4*g+3] = fmaf( se, x1, c * x3);
    }
}
template <int GB>  // sign from g bit GB (GB=0 -> lane9, GB=1 -> lane8)
__device__ __forceinline__ void applyGg(float* v, float c, float s) {
#pragma unroll
    for (int g = 0; g < 4; g++) {
        float se = (g & (1 << GB)) ? s : -s;
        float x1 = v[4*g+1], x3 = v[4*g+3];
        v[4*g+1] = fmaf(-se, x3, c * x1);
        v[4*g+3] = fmaf( se, x1, c * x3);
    }
}

// angle-vector spec tables (compile-time):
//  0.. 8 : stage0 deltas  row(0,n)-row(0,n-1), n=1..9
//  9..17 : stage1 deltas  row(1,n)-row(1,n-1), n=1..9
//  18,19 : entries  row(0,0), row(1,0)
//  20,21 : trailing row(0,9), row(1,9)
__device__ constexpr int aIdx[NIDX] = {1,2,3,4,5,6,7,8,9, 11,12,13,14,15,16,17,18,19, 0, 10, 9, 19};
__device__ constexpr int bIdx[NIDX] = {0,1,2,3,4,5,6,7,8, 10,11,12,13,14,15,16,17,18, -1,-1,-1,-1};

__global__ void __launch_bounds__(NTH, 1) rvqe_kernel(
    const int*   __restrict__ inputs,   // (64, 9, 6) int32
    const float* __restrict__ ua,       // (2, 10)
    const float* __restrict__ nth,      // (2, 10, 11)
    float*       __restrict__ out,
    int out_size)
{
    __shared__ float exch[NTH * EP];
    __shared__ float uc[20], us[20];
    __shared__ float dcs[NIDX][4], dss[NIDX][4];   // delta tables (lanes 8,9)
    __shared__ float gc_sm[20], gs_sm[20];
    __shared__ float probs_sm[64];
    __shared__ int   tIdx[TT];

    const int t = threadIdx.x;
    const int b = blockIdx.x;
    const int* inb = inputs + b * TT * 6;

    // ---- precompute ----
    if (t < 20) {
        float c, s; sincosf(0.5f * ua[t], &s, &c);
        uc[t] = c; us[t] = s;
        float cg, sg; sincosf(0.5f * nth[t * 11 + (t % 10)], &sg, &cg);
        gc_sm[t] = cg; gs_sm[t] = sg;
    }
    // delta part: g bit0 = lane9 (A[9]), g bit1 = lane8 (A[8])
    for (int j = t; j < NIDX * 4; j += NTH) {
        int idx = j >> 2, g = j & 3;
        const float* A = nth + aIdx[idx] * 11;
        const float* Bp = (bIdx[idx] >= 0) ? (nth + bIdx[idx] * 11) : nullptr;
        float d = 0.f;
        if (g & 1) d += A[9] - (Bp ? Bp[9] : 0.f);
        if (g & 2) d += A[8] - (Bp ? Bp[8] : 0.f);
        float c, s; sincosf(0.5f * d, &s, &c);
        dcs[idx][g] = c; dss[idx][g] = s;
    }
    if (t < TT) {
        int idx = 0;
#pragma unroll
        for (int i = 0; i < 6; i++) idx |= (inb[t * 6 + i] & 1) << (5 - i);
        tIdx[t] = idx;
    }

    // per-thread base trig in REGISTERS (lane i -> t bit (7-i), i=0..7)
    float cbs[NIDX], sbs[NIDX];
#pragma unroll
    for (int idx = 0; idx < NIDX; idx++) {
        const float* A = nth + aIdx[idx] * 11;
        const float* Bp = (bIdx[idx] >= 0) ? (nth + bIdx[idx] * 11) : nullptr;
        float base = A[10] - (Bp ? Bp[10] : 0.f);
#pragma unroll
        for (int i = 0; i < 8; i++)
            if ((t >> (7 - i)) & 1) base += A[i] - (Bp ? Bp[i] : 0.f);
        float c, s; sincosf(0.5f * base, &s, &c);
        cbs[idx] = c; sbs[idx] = s;
    }
    __syncthreads();

    // ---- init state: amplitude at g = tIdx[0]<<6 -> thread tIdx[0]<<2, r=0 ----
    float v[16];
#pragma unroll
    for (int r = 0; r < 16; r++) v[r] = 0.f;
    if (t == (tIdx[0] << 2)) v[0] = 1.f;

    for (int step = 0; step < NSTEP; step++) {
#pragma unroll
        for (int s = 0; s < 2; s++) {
            const float* ucc = uc + s * 10;
            const float* uss = us + s * 10;
            // stage RYs: lanes 8,9 local; lanes 3..7 shfl; lanes 0,1 4-way; lane 2 2-way
            ry_local<3>(v, ucc[8], uss[8]);
            ry_local<2>(v, ucc[9], uss[9]);
#pragma unroll
            for (int l = 3; l <= 7; l++)
                ry_shfl(v, t, 1 << (7 - l), ucc[l], uss[l]);
            ry_smem4(v, t, ucc[0], uss[0], ucc[1], uss[1], exch);
            ry_smem1(v, t, ucc[2], uss[2], exch);

            // neuron chain: E C0 G0 T' C1 G1 ... T' C9 G9 F
            applyE(v, cbs[18 + s], sbs[18 + s], dcs[18 + s], dss[18 + s]);
            ciy_smem(v, t, 128, exch);                 // C0 (lane0 = t bit7)
            applyG(v, gc_sm[s * 10], ((t >> 7) & 1) ? gs_sm[s * 10] : -gs_sm[s * 10]);
#pragma unroll
            for (int n = 1; n < 10; n++) {
                int di = s * 9 + n - 1;
                applyT(v, cbs[di], sbs[di], dcs[di], dss[di]);
                if (n >= 8) {
                    if (n == 8) ciy_local<3>(v);       // lane8 -> r bit3
                    else        ciy_local<2>(v);       // lane9 -> r bit2
                } else if (n >= 3) {
                    ciy_shfl(v, t, 1 << (7 - n));      // lanes 3..7
                } else {
                    ciy_smem(v, t, (n == 1) ? 64 : 32, exch);  // lanes 1,2
                }
                float cg = gc_sm[s * 10 + n], sg = gs_sm[s * 10 + n];
                if (n <= 7)      applyG(v, cg, ((t >> (7 - n)) & 1) ? sg : -sg);
                else if (n == 8) applyGg<1>(v, cg, sg);
                else             applyGg<0>(v, cg, sg);
            }
            applyF(v, cbs[20 + s], sbs[20 + s], dcs[20 + s], dss[20 + s]);
        }

        // ---- probs: out index j = t >> 2 (lanes 0..5); reduce over t bits 0,1 ----
        float ssq = 0.f;
#pragma unroll
        for (int r = 0; r < 16; r++) ssq = fmaf(v[r], v[r], ssq);
        ssq += __shfl_xor_sync(0xffffffffu, ssq, 1);
        ssq += __shfl_xor_sync(0xffffffffu, ssq, 2);
        if (!(t & 3)) {
            probs_sm[t >> 2] = ssq;
            out[(b * NSTEP + step) * 64 + (t >> 2)] = ssq;
        }
        __syncthreads();

        // ---- project + normalize; cond_flips cancel across steps ----
        int tj = tIdx[step + 1];
        float invn = 1.0f / sqrtf(probs_sm[tj]);
        if ((t >> 2) == tj) {
#pragma unroll
            for (int r = 0; r < 16; r++) v[r] *= invn;
        } else {
#pragma unroll
            for (int r = 0; r < 16; r++) v[r] = 0.f;
        }
    }

    // ---- second tuple output: measured = inputs[:,1:] as float ----
    if (out_size > 32768 && t < 48) {
        out[32768 + b * 48 + t] = (float)inb[6 + t];
    }
}

} // namespace

extern "C" void kernel_launch(void* const* d_in, const int* in_sizes, int n_in,
                              void* d_out, int out_size) {
    const int*   inputs = nullptr;
    const float* ua     = nullptr;
    const float* nth    = nullptr;
    for (int i = 0; i < n_in; i++) {
        if (in_sizes[i] == 3456)      inputs = (const int*)d_in[i];
        else if (in_sizes[i] == 20)   ua     = (const float*)d_in[i];
        else if (in_sizes[i] == 220)  nth    = (const float*)d_in[i];
    }
    rvqe_kernel<<<64, NTH>>>(inputs, ua, nth, (float*)d_out, out_size);
}